// round 15
// baseline (speedup 1.0000x reference)
#include <cuda_runtime.h>
#include <cuda_bf16.h>
#include <cuda_fp16.h>
#include <cstdint>
#include <math.h>

#define VV 25000
#define EE 300
#define KP 304
#define HH 512
#define G4 2048
#define BB 128
#define TT 512
#define NJG 32
#define JBLK 16
#define HBLK 16   // batch rows per half

// ---------------- device scratch ----------------
__device__ float g_table[(size_t)VV * G4];        // ~205 MB
__device__ __half g_hf[2][BB * HH];               // fp16 h exchange
__device__ __nv_bfloat16 g_ehi[(size_t)VV * KP];
__device__ __nv_bfloat16 g_elo[(size_t)VV * KP];
__device__ __nv_bfloat16 g_whi[(size_t)G4 * KP];
__device__ __nv_bfloat16 g_wlo[(size_t)G4 * KP];
__device__ unsigned g_bar[8];

// LSTM SMEM (fp16-element offsets; stride 520): W + A(16 rows) + gsb
#define WSTR 520
#define OFF_WHI 0
#define OFF_A   (64 * WSTR)                          // 33280
#define OFF_GSB_BYTES ((64 * WSTR + 16 * WSTR) * 2)  // 83200
#define SMEM_BYTES (OFF_GSB_BYTES + 4 * 16 * 64 * 4) // 99584

// table GEMM SMEM (stride 312)
#define TSTR 312
#define T_AHI 0
#define T_ALO (64 * TSTR)
#define T_BHI (2 * 64 * TSTR)
#define T_BLO (3 * 64 * TSTR)
#define T_SMEM_BYTES (4 * 64 * TSTR * 2)

// ---------------- helpers ----------------
__device__ __forceinline__ uint32_t smem_u32(const void* p) {
  uint32_t a;
  asm("{ .reg .u64 t; cvta.to.shared.u64 t, %1; cvt.u32.u64 %0, t; }" : "=r"(a) : "l"(p));
  return a;
}
__device__ __forceinline__ void ldsm4(uint32_t& r0, uint32_t& r1, uint32_t& r2,
                                      uint32_t& r3, uint32_t addr) {
  asm volatile("ldmatrix.sync.aligned.m8n8.x4.shared.b16 {%0,%1,%2,%3}, [%4];"
               : "=r"(r0), "=r"(r1), "=r"(r2), "=r"(r3) : "r"(addr));
}
__device__ __forceinline__ void mma16816(float* c, uint32_t a0, uint32_t a1,
                                         uint32_t a2, uint32_t a3, uint32_t b0,
                                         uint32_t b1) {
  asm volatile(
      "mma.sync.aligned.m16n8k16.row.col.f32.bf16.bf16.f32 "
      "{%0,%1,%2,%3},{%4,%5,%6,%7},{%8,%9},{%0,%1,%2,%3};"
      : "+f"(c[0]), "+f"(c[1]), "+f"(c[2]), "+f"(c[3])
      : "r"(a0), "r"(a1), "r"(a2), "r"(a3), "r"(b0), "r"(b1));
}
__device__ __forceinline__ void mma16816h(float* c, uint32_t a0, uint32_t a1,
                                          uint32_t a2, uint32_t a3, uint32_t b0,
                                          uint32_t b1) {
  asm volatile(
      "mma.sync.aligned.m16n8k16.row.col.f32.f16.f16.f32 "
      "{%0,%1,%2,%3},{%4,%5,%6,%7},{%8,%9},{%0,%1,%2,%3};"
      : "+f"(c[0]), "+f"(c[1]), "+f"(c[2]), "+f"(c[3])
      : "r"(a0), "r"(a1), "r"(a2), "r"(a3), "r"(b0), "r"(b1));
}
__device__ __forceinline__ void stcg_f16(__half* p, __half v) {
  unsigned short u = *reinterpret_cast<unsigned short*>(&v);
  asm volatile("st.global.cg.u16 [%0], %1;" :: "l"(p), "h"(u) : "memory");
}
__device__ __forceinline__ float fsig(float x) { return __fdividef(1.f, 1.f + __expf(-x)); }
__device__ __forceinline__ float ftanh(float x) {
  return __fdividef(2.f, 1.f + __expf(-2.f * x)) - 1.f;
}

// ---------------------------------------------------------------------------
// fused split of emb (VV rows) and W_ih (G4 rows) -> bf16 hi/lo padded KP=304
// ---------------------------------------------------------------------------
__global__ void conv_split_all_kernel(const float* __restrict__ emb,
                                      const float* __restrict__ W_ih) {
  const int idx = blockIdx.x * 256 + threadIdx.x;
  if (idx >= (VV + G4) * 76) return;
  const int r = idx / 76, q = idx - r * 76;
  const float* src;
  __nv_bfloat16 *hi, *lo;
  if (r < VV) {
    src = emb + (size_t)r * EE;
    hi = g_ehi + (size_t)r * KP;
    lo = g_elo + (size_t)r * KP;
  } else {
    const int rr = r - VV;
    src = W_ih + (size_t)rr * EE;
    hi = g_whi + (size_t)rr * KP;
    lo = g_wlo + (size_t)rr * KP;
  }
  float4 v = make_float4(0.f, 0.f, 0.f, 0.f);
  if (q < 75) v = *(const float4*)(src + q * 4);
  const float vv[4] = {v.x, v.y, v.z, v.w};
  __nv_bfloat16 hb[4], lb[4];
#pragma unroll
  for (int i = 0; i < 4; i++) {
    hb[i] = __float2bfloat16(vv[i]);
    lb[i] = __float2bfloat16(vv[i] - __bfloat162float(hb[i]));
  }
  *(uint2*)(hi + q * 4) = *(uint2*)hb;
  *(uint2*)(lo + q * 4) = *(uint2*)lb;
}

// ---------------------------------------------------------------------------
// table GEMM (bf16-split HMMA): table[v][g] = emb[v].W_ih[g] + bias
// ---------------------------------------------------------------------------
__global__ __launch_bounds__(256, 1) void table_mma_kernel(
    const float* __restrict__ b_ih, const float* __restrict__ b_hh) {
  extern __shared__ __align__(16) char smem[];
  __nv_bfloat16* sb = (__nv_bfloat16*)smem;
  const int m0v = blockIdx.y * 64;
  const int n0g = blockIdx.x * 64;
  const int tid = threadIdx.x;
  const int w = tid >> 5, lane = tid & 31;

  for (int i = tid; i < 2432; i += 256) {
    const int r = i / 38, u = i - r * 38;
    const int v = m0v + r;
    uint4 hv = make_uint4(0, 0, 0, 0), lv = hv;
    if (v < VV) {
      hv = *(const uint4*)(g_ehi + (size_t)v * KP + u * 8);
      lv = *(const uint4*)(g_elo + (size_t)v * KP + u * 8);
    }
    *(uint4*)(sb + T_AHI + r * TSTR + u * 8) = hv;
    *(uint4*)(sb + T_ALO + r * TSTR + u * 8) = lv;
    const int g = n0g + r;
    *(uint4*)(sb + T_BHI + r * TSTR + u * 8) =
        *(const uint4*)(g_whi + (size_t)g * KP + u * 8);
    *(uint4*)(sb + T_BLO + r * TSTR + u * 8) =
        *(const uint4*)(g_wlo + (size_t)g * KP + u * 8);
  }
  __syncthreads();

  const int mrow = (w & 1) << 5;
  const int nb = (w >> 1) << 4;
  const int sel = lane >> 3, li = lane & 7;
  const uint32_t s0 = smem_u32(sb);
  const int aoff0 = (mrow + li + ((sel & 1) << 3)) * TSTR + ((sel >> 1) << 3);
  const int aoff1 = aoff0 + 16 * TSTR;
  const int boff = (nb + li + ((sel >> 1) << 3)) * TSTR + ((sel & 1) << 3);
  const uint32_t aAhi0 = s0 + (uint32_t)(T_AHI + aoff0) * 2;
  const uint32_t aAhi1 = s0 + (uint32_t)(T_AHI + aoff1) * 2;
  const uint32_t aAlo0 = s0 + (uint32_t)(T_ALO + aoff0) * 2;
  const uint32_t aAlo1 = s0 + (uint32_t)(T_ALO + aoff1) * 2;
  const uint32_t aBhi = s0 + (uint32_t)(T_BHI + boff) * 2;
  const uint32_t aBlo = s0 + (uint32_t)(T_BLO + boff) * 2;

  float accA[4] = {0, 0, 0, 0}, accB[4] = {0, 0, 0, 0};
  float accC[4] = {0, 0, 0, 0}, accD[4] = {0, 0, 0, 0};
#pragma unroll
  for (int ks = 0; ks < 19; ks++) {
    const uint32_t kb = (uint32_t)ks * 32;
    uint32_t h0, h1, h2, h3, l0, l1, l2, l3, p0, p1, p2, p3, q0, q1, q2, q3;
    ldsm4(p0, p1, p2, p3, aBhi + kb);
    ldsm4(q0, q1, q2, q3, aBlo + kb);
    ldsm4(h0, h1, h2, h3, aAhi0 + kb);
    ldsm4(l0, l1, l2, l3, aAlo0 + kb);
    mma16816(accA, h0, h1, h2, h3, p0, p1);
    mma16816(accB, h0, h1, h2, h3, p2, p3);
    mma16816(accA, h0, h1, h2, h3, q0, q1);
    mma16816(accB, h0, h1, h2, h3, q2, q3);
    mma16816(accA, l0, l1, l2, l3, p0, p1);
    mma16816(accB, l0, l1, l2, l3, p2, p3);
    ldsm4(h0, h1, h2, h3, aAhi1 + kb);
    ldsm4(l0, l1, l2, l3, aAlo1 + kb);
    mma16816(accC, h0, h1, h2, h3, p0, p1);
    mma16816(accD, h0, h1, h2, h3, p2, p3);
    mma16816(accC, h0, h1, h2, h3, q0, q1);
    mma16816(accD, h0, h1, h2, h3, q2, q3);
    mma16816(accC, l0, l1, l2, l3, p0, p1);
    mma16816(accD, l0, l1, l2, l3, p2, p3);
  }

  const int cA = n0g + nb + 2 * (lane & 3);
  const int cB = cA + 8;
  const float biA0 = b_ih[cA] + b_hh[cA], biA1 = b_ih[cA + 1] + b_hh[cA + 1];
  const float biB0 = b_ih[cB] + b_hh[cB], biB1 = b_ih[cB + 1] + b_hh[cB + 1];
  const int r0 = m0v + mrow + (lane >> 2);
#pragma unroll
  for (int mt = 0; mt < 2; mt++) {
    const float* aN = mt ? accC : accA;
    const float* aB2 = mt ? accD : accB;
    const int rr = r0 + mt * 16;
    if (rr < VV) {
      *(float2*)(g_table + (size_t)rr * G4 + cA) = make_float2(aN[0] + biA0, aN[1] + biA1);
      *(float2*)(g_table + (size_t)rr * G4 + cB) = make_float2(aB2[0] + biB0, aB2[1] + biB1);
    }
    if (rr + 8 < VV) {
      *(float2*)(g_table + (size_t)(rr + 8) * G4 + cA) = make_float2(aN[2] + biA0, aN[3] + biA1);
      *(float2*)(g_table + (size_t)(rr + 8) * G4 + cB) = make_float2(aB2[2] + biB0, aB2[3] + biB1);
    }
  }
}

// ---------------------------------------------------------------------------
__global__ void split_h0_kernel(const float* __restrict__ h0) {
  const int i = blockIdx.x * 256 + threadIdx.x;
  g_hf[0][i] = __float2half(h0[i]);
}

// ---------------------------------------------------------------------------
// persistent LSTM: 128 CTAs x 256 threads, single-pass fp16, W in registers.
// Each CTA runs TWO independent 16-row halves (groups bp, bp+4) alternately;
// each half's barrier poll is separated from its release by the other half's
// processing -> barrier RTT + h L2 turnaround hidden behind real work.
// Warp = (ng, kh): M16 x N32 x K128 per half.
// ---------------------------------------------------------------------------
__global__ __launch_bounds__(256, 1) void lstm_mma_kernel(
    const int* __restrict__ x, const float* __restrict__ W_hh,
    const float* __restrict__ c0, float* __restrict__ out) {
  extern __shared__ __align__(16) char smem[];
  __half* sb = (__half*)smem;
  float* gsb = (float*)(smem + OFF_GSB_BYTES);   // [4][16][64] fp32

  const int blk = blockIdx.x;
  const int jg = blk & (NJG - 1);
  const int bp = blk >> 5;                       // 0..3
  const int j0 = jg * JBLK;
  const int tid = threadIdx.x;
  const int w = tid >> 5, lane = tid & 31;

  const int b0h[2] = {bp * HBLK, 64 + bp * HBLK};
  const int bgh[2] = {bp, bp + 4};

  // W -> SMEM fp16 (row c = gate col 0..63, contiguous K, stride 520)
  for (int i = tid; i < 64 * HH; i += 256) {
    const int c = i >> 9, k = i & 511;
    const int g = ((c >> 4) << 9) + j0 + (c & 15);
    sb[OFF_WHI + c * WSTR + k] = __float2half(W_hh[(size_t)g * HH + k]);
  }

  // activation ownership: 1 (b,j) pair per thread per half
  const int lb = tid >> 4, jj = tid & 15;
  float cstv[2];
  cstv[0] = c0[(size_t)(b0h[0] + lb) * HH + j0 + jj];
  cstv[1] = c0[(size_t)(b0h[1] + lb) * HH + j0 + jj];

  // warp tile: ng = N-half (32 cols), kh = K-quarter (128 elems)
  const int ng = w & 1, kh = w >> 1;
  const int nb = ng << 5;
  const int kbase = kh << 7;
  const int sel = lane >> 3, li = lane & 7;
  const uint32_t smem0 = smem_u32(sb);

  const int ao = (li + ((sel & 1) << 3)) * WSTR + kbase + ((sel >> 1) << 3);
  const uint32_t aA = smem0 + (uint32_t)(OFF_A + ao) * 2;
  uint32_t aWhi[2];
#pragma unroll
  for (int nt = 0; nt < 2; nt++) {
    const int bo = (nb + nt * 16 + li + ((sel >> 1) << 3)) * WSTR + kbase + ((sel & 1) << 3);
    aWhi[nt] = smem0 + (uint32_t)(OFF_WHI + bo) * 2;
  }

  // A-load indices: 4 uint4 per thread (16 rows x 64 uint4 = 1024)
  const int lr[4] = {tid >> 6, (tid + 256) >> 6, (tid + 512) >> 6, (tid + 768) >> 6};
  const int lu = tid & 63;

  __syncthreads();   // W staged

  // preload W fragments into registers (loop-invariant, 64 regs)
  uint32_t wp[2][8][4];
#pragma unroll
  for (int nt = 0; nt < 2; nt++)
#pragma unroll
    for (int ku = 0; ku < 8; ku++)
      ldsm4(wp[nt][ku][0], wp[nt][ku][1], wp[nt][ku][2], wp[nt][ku][3],
            aWhi[nt] + (uint32_t)ku * 32);

  for (int t = 0; t < TT; t++) {
    const int rb = t & 1, wb = rb ^ 1;

#pragma unroll 1
    for (int hf = 0; hf < 2; hf++) {
      const int b0 = b0h[hf];

      // --- poll this half's barrier (released after the other half last step) ---
      if (t > 0) {
        if (tid == 0) {
          const unsigned tgt = (unsigned)t * 32u;
          unsigned v;
          do {
            asm volatile("ld.acquire.gpu.global.u32 %0, [%1];"
                         : "=r"(v) : "l"(&g_bar[bgh[hf]]) : "memory");
          } while (v < tgt);
        }
        __syncthreads();
      }

      // --- A load (16 rows x 512 fp16 = 16 KB) ---
      {
        const uint4* srcF = (const uint4*)(g_hf[rb] + (size_t)b0 * HH);
#pragma unroll
        for (int it = 0; it < 4; it++)
          *(uint4*)(sb + OFF_A + lr[it] * WSTR + lu * 8) = __ldcg(srcF + lr[it] * 64 + lu);
      }
      __syncthreads();

      // gx gather (independent; lands under the MMA loop)
      const int mytok = __ldg(x + (size_t)(b0 + lb) * TT + t);
      const float* trow = g_table + (size_t)mytok * G4 + j0 + jj;
      const float gxi = __ldg(trow), gxf = __ldg(trow + 512);
      const float gxg = __ldg(trow + 1024), gxo = __ldg(trow + 1536);

      // --- MMA: M16 x N32 x K128, single fp16 pass ---
      float acc[4][4];
#pragma unroll
      for (int n = 0; n < 4; n++)
#pragma unroll
        for (int e = 0; e < 4; e++) acc[n][e] = 0.f;

#pragma unroll
      for (int ku = 0; ku < 8; ku++) {
        uint32_t a[4];
        ldsm4(a[0], a[1], a[2], a[3], aA + (uint32_t)ku * 32);
        mma16816h(acc[0], a[0], a[1], a[2], a[3], wp[0][ku][0], wp[0][ku][1]);
        mma16816h(acc[1], a[0], a[1], a[2], a[3], wp[0][ku][2], wp[0][ku][3]);
        mma16816h(acc[2], a[0], a[1], a[2], a[3], wp[1][ku][0], wp[1][ku][1]);
        mma16816h(acc[3], a[0], a[1], a[2], a[3], wp[1][ku][2], wp[1][ku][3]);
      }

      // --- partials -> gsb[kh][row][col] ---
      {
        float* gk = gsb + kh * 1024;
        const int g = lane >> 2, tg2 = (lane & 3) * 2;
#pragma unroll
        for (int n = 0; n < 4; n++) {
          const int col = nb + n * 8 + tg2;
          *(float2*)(gk + g * 64 + col) = make_float2(acc[n][0], acc[n][1]);
          *(float2*)(gk + (8 + g) * 64 + col) = make_float2(acc[n][2], acc[n][3]);
        }
      }
      __syncthreads();

      // --- activation: 1 pair/thread, sum 4 K-partials ---
      {
        const int r0 = lb * 64 + jj;
        const float gi = gsb[r0] + gsb[1024 + r0] + gsb[2048 + r0] + gsb[3072 + r0] + gxi;
        const float gf = gsb[r0 + 16] + gsb[1024 + r0 + 16] + gsb[2048 + r0 + 16] + gsb[3072 + r0 + 16] + gxf;
        const float gg = gsb[r0 + 32] + gsb[1024 + r0 + 32] + gsb[2048 + r0 + 32] + gsb[3072 + r0 + 32] + gxg;
        const float go = gsb[r0 + 48] + gsb[1024 + r0 + 48] + gsb[2048 + r0 + 48] + gsb[3072 + r0 + 48] + gxo;
        const float ii = fsig(gi), ff = fsig(gf), gc = ftanh(gg), oo = fsig(go);
        cstv[hf] = ff * cstv[hf] + ii * gc;
        const float hn = oo * ftanh(cstv[hf]);
        const size_t idx = (size_t)(b0 + lb) * HH + j0 + jj;
        stcg_f16(&g_hf[wb][idx], __float2half(hn));
        if (t == TT - 1) { out[128 + idx] = hn; out[128 + 65536 + idx] = cstv[hf]; }
      }
      __syncthreads();   // all h stores issued before release (and gsb reads done)

      // --- release this half's barrier for step t+1 ---
      if (t < TT - 1 && tid == 0) {
        asm volatile("red.add.release.gpu.global.u32 [%0], %1;"
                     :: "l"(&g_bar[bgh[hf]]), "r"(1u) : "memory");
      }
    }
  }
}

// ---------------------------------------------------------------------------
__global__ void y_kernel(const float* __restrict__ fc_w,
                         const float* __restrict__ fc_b, float* __restrict__ out) {
  const int b = blockIdx.x;
  const int tid = threadIdx.x;
  const float* hr = out + 128 + (size_t)b * HH;
  float s = 0.f;
  for (int k = tid; k < HH; k += 128) s += hr[k] * fc_w[k];
#pragma unroll
  for (int o = 16; o; o >>= 1) s += __shfl_down_sync(0xffffffffu, s, o);
  __shared__ float red[4];
  if ((tid & 31) == 0) red[tid >> 5] = s;
  __syncthreads();
  if (tid == 0) out[b] = red[0] + red[1] + red[2] + red[3] + fc_b[0];
}

// ---------------------------------------------------------------------------
extern "C" void kernel_launch(void* const* d_in, const int* in_sizes, int n_in,
                              void* d_out, int out_size) {
  const int*   x    = (const int*)d_in[0];
  const float* h0   = (const float*)d_in[1];
  const float* c0   = (const float*)d_in[2];
  const float* emb  = (const float*)d_in[3];
  const float* W_ih = (const float*)d_in[4];
  const float* W_hh = (const float*)d_in[5];
  const float* b_ih = (const float*)d_in[6];
  const float* b_hh = (const float*)d_in[7];
  const float* fc_w = (const float*)d_in[8];
  const float* fc_b = (const float*)d_in[9];
  float* out = (float*)d_out;

  cudaFuncSetAttribute(lstm_mma_kernel, cudaFuncAttributeMaxDynamicSharedMemorySize,
                       SMEM_BYTES);
  cudaFuncSetAttribute(table_mma_kernel, cudaFuncAttributeMaxDynamicSharedMemorySize,
                       T_SMEM_BYTES);

  void* bar_p = nullptr;
  cudaGetSymbolAddress(&bar_p, g_bar);
  cudaMemsetAsync(bar_p, 0, sizeof(unsigned) * 8);                              // 0

  conv_split_all_kernel<<<((VV + G4) * 76 + 255) / 256, 256>>>(emb, W_ih);      // 1
  table_mma_kernel<<<dim3(G4 / 64, (VV + 63) / 64), 256, T_SMEM_BYTES>>>(b_ih, b_hh); // 2
  split_h0_kernel<<<256, 256>>>(h0);                                            // 3
  lstm_mma_kernel<<<128, 256, SMEM_BYTES>>>(x, W_hh, c0, out);                  // 4
  y_kernel<<<BB, 128>>>(fc_w, fc_b, out);                                       // 5
}

// round 16
// speedup vs baseline: 1.4671x; 1.4671x over previous
#include <cuda_runtime.h>
#include <cuda_bf16.h>
#include <cuda_fp16.h>
#include <cstdint>
#include <math.h>

#define VV 25000
#define EE 300
#define KP 304
#define HH 512
#define G4 2048
#define BB 128
#define TT 512
#define NBG 4
#define NJG 32
#define BBLK 32
#define JBLK 16

// ---------------- device scratch ----------------
__device__ float g_table[(size_t)VV * G4];        // ~205 MB
__device__ __half g_hf[2][BB * HH];               // fp16 h exchange
__device__ __half g_ef[(size_t)VV * KP];          // emb fp16 (padded)
__device__ __half g_wf[(size_t)G4 * KP];          // W_ih fp16 (padded)
__device__ unsigned g_bar[8];

// LSTM SMEM (fp16-element offsets; stride 520): W + A + gsb  (R14 layout)
#define WSTR 520
#define OFF_WHI 0
#define OFF_A   (64 * WSTR)                          // 33280
#define OFF_GSB_BYTES ((64 * WSTR + 32 * WSTR) * 2)  // 99840
#define SMEM_BYTES (OFF_GSB_BYTES + 4 * 32 * 64 * 4) // 132608

// table GEMM SMEM (stride 312, fp16 single-pass)
#define TSTR 312
#define T_A 0
#define T_B (64 * TSTR)
#define T_SMEM_BYTES (2 * 64 * TSTR * 2)   // 79872

// ---------------- helpers ----------------
__device__ __forceinline__ uint32_t smem_u32(const void* p) {
  uint32_t a;
  asm("{ .reg .u64 t; cvta.to.shared.u64 t, %1; cvt.u32.u64 %0, t; }" : "=r"(a) : "l"(p));
  return a;
}
__device__ __forceinline__ void ldsm4(uint32_t& r0, uint32_t& r1, uint32_t& r2,
                                      uint32_t& r3, uint32_t addr) {
  asm volatile("ldmatrix.sync.aligned.m8n8.x4.shared.b16 {%0,%1,%2,%3}, [%4];"
               : "=r"(r0), "=r"(r1), "=r"(r2), "=r"(r3) : "r"(addr));
}
__device__ __forceinline__ void mma16816h(float* c, uint32_t a0, uint32_t a1,
                                          uint32_t a2, uint32_t a3, uint32_t b0,
                                          uint32_t b1) {
  asm volatile(
      "mma.sync.aligned.m16n8k16.row.col.f32.f16.f16.f32 "
      "{%0,%1,%2,%3},{%4,%5,%6,%7},{%8,%9},{%0,%1,%2,%3};"
      : "+f"(c[0]), "+f"(c[1]), "+f"(c[2]), "+f"(c[3])
      : "r"(a0), "r"(a1), "r"(a2), "r"(a3), "r"(b0), "r"(b1));
}
__device__ __forceinline__ void stcg_f16(__half* p, __half v) {
  unsigned short u = *reinterpret_cast<unsigned short*>(&v);
  asm volatile("st.global.cg.u16 [%0], %1;" :: "l"(p), "h"(u) : "memory");
}
__device__ __forceinline__ float fsig(float x) { return __fdividef(1.f, 1.f + __expf(-x)); }
__device__ __forceinline__ float ftanh(float x) {
  return __fdividef(2.f, 1.f + __expf(-2.f * x)) - 1.f;
}

// ---------------------------------------------------------------------------
// fused fp16 convert of emb (VV rows) and W_ih (G4 rows), padded to KP=304
// ---------------------------------------------------------------------------
__global__ void conv_f16_kernel(const float* __restrict__ emb,
                                const float* __restrict__ W_ih) {
  const int idx = blockIdx.x * 256 + threadIdx.x;
  if (idx >= (VV + G4) * 76) return;
  const int r = idx / 76, q = idx - r * 76;
  const float* src;
  __half* dst;
  if (r < VV) {
    src = emb + (size_t)r * EE;
    dst = g_ef + (size_t)r * KP;
  } else {
    const int rr = r - VV;
    src = W_ih + (size_t)rr * EE;
    dst = g_wf + (size_t)rr * KP;
  }
  float4 v = make_float4(0.f, 0.f, 0.f, 0.f);
  if (q < 75) v = *(const float4*)(src + q * 4);
  __half h[4] = {__float2half(v.x), __float2half(v.y),
                 __float2half(v.z), __float2half(v.w)};
  *(uint2*)(dst + q * 4) = *(uint2*)h;
}

// ---------------------------------------------------------------------------
// table GEMM (single-pass fp16 HMMA): table[v][g] = emb[v].W_ih[g] + bias
// tile M=64 x N=64, K=304; 8 warps = 2M(32) x 4N(16)
// ---------------------------------------------------------------------------
__global__ __launch_bounds__(256, 1) void table_mma_kernel(
    const float* __restrict__ b_ih, const float* __restrict__ b_hh) {
  extern __shared__ __align__(16) char smem[];
  __half* sb = (__half*)smem;
  const int m0v = blockIdx.y * 64;
  const int n0g = blockIdx.x * 64;
  const int tid = threadIdx.x;
  const int w = tid >> 5, lane = tid & 31;

  for (int i = tid; i < 2432; i += 256) {
    const int r = i / 38, u = i - r * 38;
    const int v = m0v + r;
    uint4 av = make_uint4(0, 0, 0, 0);
    if (v < VV) av = *(const uint4*)(g_ef + (size_t)v * KP + u * 8);
    *(uint4*)(sb + T_A + r * TSTR + u * 8) = av;
    const int g = n0g + r;
    *(uint4*)(sb + T_B + r * TSTR + u * 8) =
        *(const uint4*)(g_wf + (size_t)g * KP + u * 8);
  }
  __syncthreads();

  const int mrow = (w & 1) << 5;
  const int nb = (w >> 1) << 4;
  const int sel = lane >> 3, li = lane & 7;
  const uint32_t s0 = smem_u32(sb);
  const int aoff0 = (mrow + li + ((sel & 1) << 3)) * TSTR + ((sel >> 1) << 3);
  const int aoff1 = aoff0 + 16 * TSTR;
  const int boff = (nb + li + ((sel >> 1) << 3)) * TSTR + ((sel & 1) << 3);
  const uint32_t aA0 = s0 + (uint32_t)(T_A + aoff0) * 2;
  const uint32_t aA1 = s0 + (uint32_t)(T_A + aoff1) * 2;
  const uint32_t aB = s0 + (uint32_t)(T_B + boff) * 2;

  float accA[4] = {0, 0, 0, 0}, accB[4] = {0, 0, 0, 0};
  float accC[4] = {0, 0, 0, 0}, accD[4] = {0, 0, 0, 0};
#pragma unroll
  for (int ks = 0; ks < 19; ks++) {
    const uint32_t kb = (uint32_t)ks * 32;
    uint32_t a0, a1, a2, a3, c0, c1, c2, c3, p0, p1, p2, p3;
    ldsm4(p0, p1, p2, p3, aB + kb);
    ldsm4(a0, a1, a2, a3, aA0 + kb);
    ldsm4(c0, c1, c2, c3, aA1 + kb);
    mma16816h(accA, a0, a1, a2, a3, p0, p1);
    mma16816h(accB, a0, a1, a2, a3, p2, p3);
    mma16816h(accC, c0, c1, c2, c3, p0, p1);
    mma16816h(accD, c0, c1, c2, c3, p2, p3);
  }

  const int cA = n0g + nb + 2 * (lane & 3);
  const int cB2 = cA + 8;
  const float biA0 = b_ih[cA] + b_hh[cA], biA1 = b_ih[cA + 1] + b_hh[cA + 1];
  const float biB0 = b_ih[cB2] + b_hh[cB2], biB1 = b_ih[cB2 + 1] + b_hh[cB2 + 1];
  const int r0 = m0v + mrow + (lane >> 2);
#pragma unroll
  for (int mt = 0; mt < 2; mt++) {
    const float* aN = mt ? accC : accA;
    const float* aB3 = mt ? accD : accB;
    const int rr = r0 + mt * 16;
    if (rr < VV) {
      *(float2*)(g_table + (size_t)rr * G4 + cA) = make_float2(aN[0] + biA0, aN[1] + biA1);
      *(float2*)(g_table + (size_t)rr * G4 + cB2) = make_float2(aB3[0] + biB0, aB3[1] + biB1);
    }
    if (rr + 8 < VV) {
      *(float2*)(g_table + (size_t)(rr + 8) * G4 + cA) = make_float2(aN[2] + biA0, aN[3] + biA1);
      *(float2*)(g_table + (size_t)(rr + 8) * G4 + cB2) = make_float2(aB3[2] + biB0, aB3[3] + biB1);
    }
  }
}

// ---------------------------------------------------------------------------
__global__ void split_h0_kernel(const float* __restrict__ h0) {
  const int i = blockIdx.x * 256 + threadIdx.x;
  g_hf[0][i] = __float2half(h0[i]);
}

// ---------------------------------------------------------------------------
// persistent LSTM (R14 config, verbatim): 128 CTAs x 256 threads.
// Warp = (ng, kh): M32 x N32 x K128, single-pass fp16, W in registers.
// ---------------------------------------------------------------------------
__global__ __launch_bounds__(256, 1) void lstm_mma_kernel(
    const int* __restrict__ x, const float* __restrict__ W_hh,
    const float* __restrict__ c0, float* __restrict__ out) {
  extern __shared__ __align__(16) char smem[];
  __half* sb = (__half*)smem;
  float* gsb = (float*)(smem + OFF_GSB_BYTES);   // [4][32][64] fp32
  __shared__ int tok[BBLK];

  const int blk = blockIdx.x;
  const int jg = blk & (NJG - 1);
  const int bg = blk >> 5;
  const int b0 = bg * BBLK;
  const int j0 = jg * JBLK;
  const int tid = threadIdx.x;
  const int w = tid >> 5, lane = tid & 31;

  // W -> SMEM fp16 (row c = gate col 0..63, contiguous K, stride 520)
  for (int i = tid; i < 64 * HH; i += 256) {
    const int c = i >> 9, k = i & 511;
    const int g = ((c >> 4) << 9) + j0 + (c & 15);
    sb[OFF_WHI + c * WSTR + k] = __float2half(W_hh[(size_t)g * HH + k]);
  }

  const int lb0 = tid >> 4,         jj0 = tid & 15;
  const int lb1 = (tid + 256) >> 4, jj1 = (tid + 256) & 15;
  float cst0 = c0[(size_t)(b0 + lb0) * HH + j0 + jj0];
  float cst1 = c0[(size_t)(b0 + lb1) * HH + j0 + jj1];

  const int ng = w & 1, kh = w >> 1;
  const int nb = ng << 5;
  const int kbase = kh << 7;
  const int sel = lane >> 3, li = lane & 7;
  const uint32_t smem0 = smem_u32(sb);

  uint32_t aA[2];
#pragma unroll
  for (int m = 0; m < 2; m++) {
    const int ao = (m * 16 + li + ((sel & 1) << 3)) * WSTR + kbase + ((sel >> 1) << 3);
    aA[m] = smem0 + (uint32_t)(OFF_A + ao) * 2;
  }
  uint32_t aWhi[2];
#pragma unroll
  for (int nt = 0; nt < 2; nt++) {
    const int bo = (nb + nt * 16 + li + ((sel >> 1) << 3)) * WSTR + kbase + ((sel & 1) << 3);
    aWhi[nt] = smem0 + (uint32_t)(OFF_WHI + bo) * 2;
  }

  __syncthreads();   // W staged

  uint32_t wp[2][8][4];
#pragma unroll
  for (int nt = 0; nt < 2; nt++)
#pragma unroll
    for (int ku = 0; ku < 8; ku++)
      ldsm4(wp[nt][ku][0], wp[nt][ku][1], wp[nt][ku][2], wp[nt][ku][3],
            aWhi[nt] + (uint32_t)ku * 32);

  for (int t = 0; t < TT; t++) {
    const int rb = t & 1, wb = rb ^ 1;
    if (tid < BBLK) tok[tid] = __ldg(x + (size_t)(b0 + tid) * TT + t);

    {
      const uint4* srcF = (const uint4*)(g_hf[rb] + (size_t)b0 * HH);
#pragma unroll
      for (int it = 0; it < 8; it++) {
        const int i = tid + it * 256;
        const int r = i >> 6, u = i & 63;
        *(uint4*)(sb + OFF_A + r * WSTR + u * 8) = __ldcg(srcF + r * 64 + u);
      }
    }
    __syncthreads();

    const float* trow0 = g_table + (size_t)tok[lb0] * G4 + j0 + jj0;
    const float* trow1 = g_table + (size_t)tok[lb1] * G4 + j0 + jj1;
    const float gx0i = __ldg(trow0), gx0f = __ldg(trow0 + 512);
    const float gx0g = __ldg(trow0 + 1024), gx0o = __ldg(trow0 + 1536);
    const float gx1i = __ldg(trow1), gx1f = __ldg(trow1 + 512);
    const float gx1g = __ldg(trow1 + 1024), gx1o = __ldg(trow1 + 1536);

    float acc[2][4][4];
#pragma unroll
    for (int m = 0; m < 2; m++)
#pragma unroll
      for (int n = 0; n < 4; n++)
#pragma unroll
        for (int e = 0; e < 4; e++) acc[m][n][e] = 0.f;

#pragma unroll
    for (int ku = 0; ku < 8; ku++) {
      const uint32_t kb = (uint32_t)ku * 32;
      uint32_t a0[4], a1[4];
      ldsm4(a0[0], a0[1], a0[2], a0[3], aA[0] + kb);
      ldsm4(a1[0], a1[1], a1[2], a1[3], aA[1] + kb);
      mma16816h(acc[0][0], a0[0], a0[1], a0[2], a0[3], wp[0][ku][0], wp[0][ku][1]);
      mma16816h(acc[0][1], a0[0], a0[1], a0[2], a0[3], wp[0][ku][2], wp[0][ku][3]);
      mma16816h(acc[0][2], a0[0], a0[1], a0[2], a0[3], wp[1][ku][0], wp[1][ku][1]);
      mma16816h(acc[0][3], a0[0], a0[1], a0[2], a0[3], wp[1][ku][2], wp[1][ku][3]);
      mma16816h(acc[1][0], a1[0], a1[1], a1[2], a1[3], wp[0][ku][0], wp[0][ku][1]);
      mma16816h(acc[1][1], a1[0], a1[1], a1[2], a1[3], wp[0][ku][2], wp[0][ku][3]);
      mma16816h(acc[1][2], a1[0], a1[1], a1[2], a1[3], wp[1][ku][0], wp[1][ku][1]);
      mma16816h(acc[1][3], a1[0], a1[1], a1[2], a1[3], wp[1][ku][2], wp[1][ku][3]);
    }

    {
      float* gk = gsb + kh * 2048;
      const int g = lane >> 2, tg2 = (lane & 3) * 2;
#pragma unroll
      for (int m = 0; m < 2; m++)
#pragma unroll
        for (int n = 0; n < 4; n++) {
          const int col = nb + n * 8 + tg2;
          *(float2*)(gk + (m * 16 + g) * 64 + col) =
              make_float2(acc[m][n][0], acc[m][n][1]);
          *(float2*)(gk + (m * 16 + 8 + g) * 64 + col) =
              make_float2(acc[m][n][2], acc[m][n][3]);
        }
    }
    __syncthreads();

    {
      const int r0 = lb0 * 64;
      const float gi = gsb[r0 + jj0] + gsb[2048 + r0 + jj0] + gsb[4096 + r0 + jj0] + gsb[6144 + r0 + jj0] + gx0i;
      const float gf = gsb[r0 + 16 + jj0] + gsb[2048 + r0 + 16 + jj0] + gsb[4096 + r0 + 16 + jj0] + gsb[6144 + r0 + 16 + jj0] + gx0f;
      const float gg = gsb[r0 + 32 + jj0] + gsb[2048 + r0 + 32 + jj0] + gsb[4096 + r0 + 32 + jj0] + gsb[6144 + r0 + 32 + jj0] + gx0g;
      const float go = gsb[r0 + 48 + jj0] + gsb[2048 + r0 + 48 + jj0] + gsb[4096 + r0 + 48 + jj0] + gsb[6144 + r0 + 48 + jj0] + gx0o;
      const float ii = fsig(gi), ff = fsig(gf), gc = ftanh(gg), oo = fsig(go);
      cst0 = ff * cst0 + ii * gc;
      const float hn = oo * ftanh(cst0);
      const size_t idx = (size_t)(b0 + lb0) * HH + j0 + jj0;
      stcg_f16(&g_hf[wb][idx], __float2half(hn));
      if (t == TT - 1) { out[128 + idx] = hn; out[128 + 65536 + idx] = cst0; }
    }
    {
      const int r1 = lb1 * 64;
      const float gi = gsb[r1 + jj1] + gsb[2048 + r1 + jj1] + gsb[4096 + r1 + jj1] + gsb[6144 + r1 + jj1] + gx1i;
      const float gf = gsb[r1 + 16 + jj1] + gsb[2048 + r1 + 16 + jj1] + gsb[4096 + r1 + 16 + jj1] + gsb[6144 + r1 + 16 + jj1] + gx1f;
      const float gg = gsb[r1 + 32 + jj1] + gsb[2048 + r1 + 32 + jj1] + gsb[4096 + r1 + 32 + jj1] + gsb[6144 + r1 + 32 + jj1] + gx1g;
      const float go = gsb[r1 + 48 + jj1] + gsb[2048 + r1 + 48 + jj1] + gsb[4096 + r1 + 48 + jj1] + gsb[6144 + r1 + 48 + jj1] + gx1o;
      const float ii = fsig(gi), ff = fsig(gf), gc = ftanh(gg), oo = fsig(go);
      cst1 = ff * cst1 + ii * gc;
      const float hn = oo * ftanh(cst1);
      const size_t idx = (size_t)(b0 + lb1) * HH + j0 + jj1;
      stcg_f16(&g_hf[wb][idx], __float2half(hn));
      if (t == TT - 1) { out[128 + idx] = hn; out[128 + 65536 + idx] = cst1; }
    }

    if (t < TT - 1) {
      __syncthreads();
      if (tid == 0) {
        asm volatile("red.add.release.gpu.global.u32 [%0], %1;"
                     :: "l"(&g_bar[bg]), "r"(1u) : "memory");
        const unsigned tgt = (unsigned)(t + 1) * (unsigned)NJG;
        unsigned v;
        do {
          asm volatile("ld.acquire.gpu.global.u32 %0, [%1];"
                       : "=r"(v) : "l"(&g_bar[bg]) : "memory");
        } while (v < tgt);
      }
      __syncthreads();
    }
  }
}

// ---------------------------------------------------------------------------
__global__ void y_kernel(const float* __restrict__ fc_w,
                         const float* __restrict__ fc_b, float* __restrict__ out) {
  const int b = blockIdx.x;
  const int tid = threadIdx.x;
  const float* hr = out + 128 + (size_t)b * HH;
  float s = 0.f;
  for (int k = tid; k < HH; k += 128) s += hr[k] * fc_w[k];
#pragma unroll
  for (int o = 16; o; o >>= 1) s += __shfl_down_sync(0xffffffffu, s, o);
  __shared__ float red[4];
  if ((tid & 31) == 0) red[tid >> 5] = s;
  __syncthreads();
  if (tid == 0) out[b] = red[0] + red[1] + red[2] + red[3] + fc_b[0];
}

// ---------------------------------------------------------------------------
extern "C" void kernel_launch(void* const* d_in, const int* in_sizes, int n_in,
                              void* d_out, int out_size) {
  const int*   x    = (const int*)d_in[0];
  const float* h0   = (const float*)d_in[1];
  const float* c0   = (const float*)d_in[2];
  const float* emb  = (const float*)d_in[3];
  const float* W_ih = (const float*)d_in[4];
  const float* W_hh = (const float*)d_in[5];
  const float* b_ih = (const float*)d_in[6];
  const float* b_hh = (const float*)d_in[7];
  const float* fc_w = (const float*)d_in[8];
  const float* fc_b = (const float*)d_in[9];
  float* out = (float*)d_out;

  cudaFuncSetAttribute(lstm_mma_kernel, cudaFuncAttributeMaxDynamicSharedMemorySize,
                       SMEM_BYTES);
  cudaFuncSetAttribute(table_mma_kernel, cudaFuncAttributeMaxDynamicSharedMemorySize,
                       T_SMEM_BYTES);

  void* bar_p = nullptr;
  cudaGetSymbolAddress(&bar_p, g_bar);
  cudaMemsetAsync(bar_p, 0, sizeof(unsigned) * 8);                              // 0

  conv_f16_kernel<<<((VV + G4) * 76 + 255) / 256, 256>>>(emb, W_ih);            // 1
  table_mma_kernel<<<dim3(G4 / 64, (VV + 63) / 64), 256, T_SMEM_BYTES>>>(b_ih, b_hh); // 2
  split_h0_kernel<<<256, 256>>>(h0);                                            // 3
  lstm_mma_kernel<<<128, 256, SMEM_BYTES>>>(x, W_hh, c0, out);                  // 4
  y_kernel<<<BB, 128>>>(fc_w, fc_b, out);                                       // 5
}

// round 17
// speedup vs baseline: 1.5446x; 1.0528x over previous
#include <cuda_runtime.h>
#include <cuda_bf16.h>
#include <cuda_fp16.h>
#include <cstdint>
#include <math.h>

#define VV 25000
#define EE 300
#define KP 304
#define HH 512
#define G4 2048
#define BB 128
#define TT 512
#define NJG 32
#define JBLK 16
#define MBLK 16   // batch rows per CTA

// ---------------- device scratch ----------------
__device__ float g_table[(size_t)VV * G4];        // ~205 MB
__device__ __half g_hf[2][BB * HH];               // fp16 h exchange
__device__ __half g_ef[(size_t)VV * KP];          // emb fp16 (padded)
__device__ __half g_wf[(size_t)G4 * KP];          // W_ih fp16 (padded)
__device__ unsigned g_bar[8];

// LSTM SMEM: W staged at offset 0 (64*520 fp16 = 66560 B), then overlaid by
// A (16*520 fp16 = 16640 B) + gsb (4*16*64 fp32 = 16384 B at byte 16640)
#define WSTR 520
#define OFF_GSB_BYTES (16 * WSTR * 2)       // 16640
#define SMEM_BYTES (64 * WSTR * 2)          // 66560 (covers both phases)

// table GEMM SMEM (stride 312, fp16 single-pass)
#define TSTR 312
#define T_A 0
#define T_B (64 * TSTR)
#define T_SMEM_BYTES (2 * 64 * TSTR * 2)

// ---------------- helpers ----------------
__device__ __forceinline__ uint32_t smem_u32(const void* p) {
  uint32_t a;
  asm("{ .reg .u64 t; cvta.to.shared.u64 t, %1; cvt.u32.u64 %0, t; }" : "=r"(a) : "l"(p));
  return a;
}
__device__ __forceinline__ void ldsm4(uint32_t& r0, uint32_t& r1, uint32_t& r2,
                                      uint32_t& r3, uint32_t addr) {
  asm volatile("ldmatrix.sync.aligned.m8n8.x4.shared.b16 {%0,%1,%2,%3}, [%4];"
               : "=r"(r0), "=r"(r1), "=r"(r2), "=r"(r3) : "r"(addr));
}
__device__ __forceinline__ void mma16816h(float* c, uint32_t a0, uint32_t a1,
                                          uint32_t a2, uint32_t a3, uint32_t b0,
                                          uint32_t b1) {
  asm volatile(
      "mma.sync.aligned.m16n8k16.row.col.f32.f16.f16.f32 "
      "{%0,%1,%2,%3},{%4,%5,%6,%7},{%8,%9},{%0,%1,%2,%3};"
      : "+f"(c[0]), "+f"(c[1]), "+f"(c[2]), "+f"(c[3])
      : "r"(a0), "r"(a1), "r"(a2), "r"(a3), "r"(b0), "r"(b1));
}
__device__ __forceinline__ void stcg_f16(__half* p, __half v) {
  unsigned short u = *reinterpret_cast<unsigned short*>(&v);
  asm volatile("st.global.cg.u16 [%0], %1;" :: "l"(p), "h"(u) : "memory");
}
__device__ __forceinline__ float fsig(float x) { return __fdividef(1.f, 1.f + __expf(-x)); }
__device__ __forceinline__ float ftanh(float x) {
  return __fdividef(2.f, 1.f + __expf(-2.f * x)) - 1.f;
}

// ---------------------------------------------------------------------------
// fused fp16 convert of emb (VV rows) and W_ih (G4 rows), padded to KP=304
// ---------------------------------------------------------------------------
__global__ void conv_f16_kernel(const float* __restrict__ emb,
                                const float* __restrict__ W_ih) {
  const int idx = blockIdx.x * 256 + threadIdx.x;
  if (idx >= (VV + G4) * 76) return;
  const int r = idx / 76, q = idx - r * 76;
  const float* src;
  __half* dst;
  if (r < VV) {
    src = emb + (size_t)r * EE;
    dst = g_ef + (size_t)r * KP;
  } else {
    const int rr = r - VV;
    src = W_ih + (size_t)rr * EE;
    dst = g_wf + (size_t)rr * KP;
  }
  float4 v = make_float4(0.f, 0.f, 0.f, 0.f);
  if (q < 75) v = *(const float4*)(src + q * 4);
  __half h[4] = {__float2half(v.x), __float2half(v.y),
                 __float2half(v.z), __float2half(v.w)};
  *(uint2*)(dst + q * 4) = *(uint2*)h;
}

// ---------------------------------------------------------------------------
// table GEMM (single-pass fp16 HMMA): table[v][g] = emb[v].W_ih[g] + bias
// ---------------------------------------------------------------------------
__global__ __launch_bounds__(256, 1) void table_mma_kernel(
    const float* __restrict__ b_ih, const float* __restrict__ b_hh) {
  extern __shared__ __align__(16) char smem[];
  __half* sb = (__half*)smem;
  const int m0v = blockIdx.y * 64;
  const int n0g = blockIdx.x * 64;
  const int tid = threadIdx.x;
  const int w = tid >> 5, lane = tid & 31;

  for (int i = tid; i < 2432; i += 256) {
    const int r = i / 38, u = i - r * 38;
    const int v = m0v + r;
    uint4 av = make_uint4(0, 0, 0, 0);
    if (v < VV) av = *(const uint4*)(g_ef + (size_t)v * KP + u * 8);
    *(uint4*)(sb + T_A + r * TSTR + u * 8) = av;
    const int g = n0g + r;
    *(uint4*)(sb + T_B + r * TSTR + u * 8) =
        *(const uint4*)(g_wf + (size_t)g * KP + u * 8);
  }
  __syncthreads();

  const int mrow = (w & 1) << 5;
  const int nb = (w >> 1) << 4;
  const int sel = lane >> 3, li = lane & 7;
  const uint32_t s0 = smem_u32(sb);
  const int aoff0 = (mrow + li + ((sel & 1) << 3)) * TSTR + ((sel >> 1) << 3);
  const int aoff1 = aoff0 + 16 * TSTR;
  const int boff = (nb + li + ((sel >> 1) << 3)) * TSTR + ((sel & 1) << 3);
  const uint32_t aA0 = s0 + (uint32_t)(T_A + aoff0) * 2;
  const uint32_t aA1 = s0 + (uint32_t)(T_A + aoff1) * 2;
  const uint32_t aB = s0 + (uint32_t)(T_B + boff) * 2;

  float accA[4] = {0, 0, 0, 0}, accB[4] = {0, 0, 0, 0};
  float accC[4] = {0, 0, 0, 0}, accD[4] = {0, 0, 0, 0};
#pragma unroll
  for (int ks = 0; ks < 19; ks++) {
    const uint32_t kb = (uint32_t)ks * 32;
    uint32_t a0, a1, a2, a3, c0, c1, c2, c3, p0, p1, p2, p3;
    ldsm4(p0, p1, p2, p3, aB + kb);
    ldsm4(a0, a1, a2, a3, aA0 + kb);
    ldsm4(c0, c1, c2, c3, aA1 + kb);
    mma16816h(accA, a0, a1, a2, a3, p0, p1);
    mma16816h(accB, a0, a1, a2, a3, p2, p3);
    mma16816h(accC, c0, c1, c2, c3, p0, p1);
    mma16816h(accD, c0, c1, c2, c3, p2, p3);
  }

  const int cA = n0g + nb + 2 * (lane & 3);
  const int cB2 = cA + 8;
  const float biA0 = b_ih[cA] + b_hh[cA], biA1 = b_ih[cA + 1] + b_hh[cA + 1];
  const float biB0 = b_ih[cB2] + b_hh[cB2], biB1 = b_ih[cB2 + 1] + b_hh[cB2 + 1];
  const int r0 = m0v + mrow + (lane >> 2);
#pragma unroll
  for (int mt = 0; mt < 2; mt++) {
    const float* aN = mt ? accC : accA;
    const float* aB3 = mt ? accD : accB;
    const int rr = r0 + mt * 16;
    if (rr < VV) {
      *(float2*)(g_table + (size_t)rr * G4 + cA) = make_float2(aN[0] + biA0, aN[1] + biA1);
      *(float2*)(g_table + (size_t)rr * G4 + cB2) = make_float2(aB3[0] + biB0, aB3[1] + biB1);
    }
    if (rr + 8 < VV) {
      *(float2*)(g_table + (size_t)(rr + 8) * G4 + cA) = make_float2(aN[2] + biA0, aN[3] + biA1);
      *(float2*)(g_table + (size_t)(rr + 8) * G4 + cB2) = make_float2(aB3[2] + biB0, aB3[3] + biB1);
    }
  }
}

// ---------------------------------------------------------------------------
__global__ void split_h0_kernel(const float* __restrict__ h0) {
  const int i = blockIdx.x * 256 + threadIdx.x;
  g_hf[0][i] = __float2half(h0[i]);
}

// ---------------------------------------------------------------------------
// persistent LSTM: 256 CTAs x 256 threads, 2 CTAs/SM (launch_bounds(256,2)).
// CTA = M16 batch rows x N64 gate cols x K512; 8 batch groups x 32 j-groups.
// Warp = (ng, kh): M16 x N32 x K128, single-pass fp16, W in registers.
// W staged in SMEM then overlaid by A + gsb (65KB total -> 2 CTAs co-resident).
// ---------------------------------------------------------------------------
__global__ __launch_bounds__(256, 2) void lstm_mma_kernel(
    const int* __restrict__ x, const float* __restrict__ W_hh,
    const float* __restrict__ c0, float* __restrict__ out) {
  extern __shared__ __align__(16) char smem[];
  __half* sb = (__half*)smem;
  float* gsb = (float*)(smem + OFF_GSB_BYTES);   // [4][16][64] fp32
  __shared__ int tok[MBLK];

  const int blk = blockIdx.x;
  const int jg = blk & (NJG - 1);
  const int bg = blk >> 5;           // 0..7
  const int b0 = bg * MBLK;
  const int j0 = jg * JBLK;
  const int tid = threadIdx.x;
  const int w = tid >> 5, lane = tid & 31;

  // stage W fp16 into SMEM (row c = gate col 0..63, contiguous K, stride 520)
  for (int i = tid; i < 64 * HH; i += 256) {
    const int c = i >> 9, k = i & 511;
    const int g = ((c >> 4) << 9) + j0 + (c & 15);
    sb[c * WSTR + k] = __float2half(W_hh[(size_t)g * HH + k]);
  }

  // activation ownership: 1 (b,j) pair per thread
  const int lb = tid >> 4, jj = tid & 15;
  float cst = c0[(size_t)(b0 + lb) * HH + j0 + jj];

  // warp tile: ng = N-half (32 cols), kh = K-quarter (128 elems)
  const int ng = w & 1, kh = w >> 1;
  const int nb = ng << 5;
  const int kbase = kh << 7;
  const int sel = lane >> 3, li = lane & 7;
  const uint32_t smem0 = smem_u32(sb);

  // A fragment addr (rows 0..15, same smem base as W stage)
  const int ao = (li + ((sel & 1) << 3)) * WSTR + kbase + ((sel >> 1) << 3);
  const uint32_t aA = smem0 + (uint32_t)ao * 2;
  uint32_t aW[2];
#pragma unroll
  for (int nt = 0; nt < 2; nt++) {
    const int bo = (nb + nt * 16 + li + ((sel >> 1) << 3)) * WSTR + kbase + ((sel & 1) << 3);
    aW[nt] = smem0 + (uint32_t)bo * 2;
  }

  // A-load indices: 4 uint4/thread (16 rows x 64 uint4)
  const int lr[4] = {tid >> 6, (tid + 256) >> 6, (tid + 512) >> 6, (tid + 768) >> 6};
  const int lu = tid & 63;

  __syncthreads();   // W staged

  // preload W fragments to registers (loop-invariant, 64 regs)
  uint32_t wp[2][8][4];
#pragma unroll
  for (int nt = 0; nt < 2; nt++)
#pragma unroll
    for (int ku = 0; ku < 8; ku++)
      ldsm4(wp[nt][ku][0], wp[nt][ku][1], wp[nt][ku][2], wp[nt][ku][3],
            aW[nt] + (uint32_t)ku * 32);
  __syncthreads();   // all warps done reading W before region reuse

  for (int t = 0; t < TT; t++) {
    const int rb = t & 1, wb = rb ^ 1;
    if (tid < MBLK) tok[tid] = __ldg(x + (size_t)(b0 + tid) * TT + t);

    // A load (16 rows x 512 fp16 = 16 KB) into W-stage region
    {
      const uint4* srcF = (const uint4*)(g_hf[rb] + (size_t)b0 * HH);
#pragma unroll
      for (int it = 0; it < 4; it++)
        *(uint4*)(sb + lr[it] * WSTR + lu * 8) = __ldcg(srcF + lr[it] * 64 + lu);
    }
    __syncthreads();

    // gx gather (hidden under MMA loop)
    const float* trow = g_table + (size_t)tok[lb] * G4 + j0 + jj;
    const float gxi = __ldg(trow), gxf = __ldg(trow + 512);
    const float gxg = __ldg(trow + 1024), gxo = __ldg(trow + 1536);

    // MMA: M16 x N32 x K128, single fp16 pass
    float acc[4][4];
#pragma unroll
    for (int n = 0; n < 4; n++)
#pragma unroll
      for (int e = 0; e < 4; e++) acc[n][e] = 0.f;

#pragma unroll
    for (int ku = 0; ku < 8; ku++) {
      uint32_t a[4];
      ldsm4(a[0], a[1], a[2], a[3], aA + (uint32_t)ku * 32);
      mma16816h(acc[0], a[0], a[1], a[2], a[3], wp[0][ku][0], wp[0][ku][1]);
      mma16816h(acc[1], a[0], a[1], a[2], a[3], wp[0][ku][2], wp[0][ku][3]);
      mma16816h(acc[2], a[0], a[1], a[2], a[3], wp[1][ku][0], wp[1][ku][1]);
      mma16816h(acc[3], a[0], a[1], a[2], a[3], wp[1][ku][2], wp[1][ku][3]);
    }
    __syncthreads();   // A reads done before gsb (overlaps A region tail)

    // partials -> gsb[kh][row][col]
    {
      float* gk = gsb + kh * 1024;
      const int g = lane >> 2, tg2 = (lane & 3) * 2;
#pragma unroll
      for (int n = 0; n < 4; n++) {
        const int col = nb + n * 8 + tg2;
        *(float2*)(gk + g * 64 + col) = make_float2(acc[n][0], acc[n][1]);
        *(float2*)(gk + (8 + g) * 64 + col) = make_float2(acc[n][2], acc[n][3]);
      }
    }
    __syncthreads();

    // activation: 1 pair/thread, sum 4 K-partials
    {
      const int r0 = lb * 64 + jj;
      const float gi = gsb[r0] + gsb[1024 + r0] + gsb[2048 + r0] + gsb[3072 + r0] + gxi;
      const float gf = gsb[r0 + 16] + gsb[1024 + r0 + 16] + gsb[2048 + r0 + 16] + gsb[3072 + r0 + 16] + gxf;
      const float gg = gsb[r0 + 32] + gsb[1024 + r0 + 32] + gsb[2048 + r0 + 32] + gsb[3072 + r0 + 32] + gxg;
      const float go = gsb[r0 + 48] + gsb[1024 + r0 + 48] + gsb[2048 + r0 + 48] + gsb[3072 + r0 + 48] + gxo;
      const float ii = fsig(gi), ff = fsig(gf), gc = ftanh(gg), oo = fsig(go);
      cst = ff * cst + ii * gc;
      const float hn = oo * ftanh(cst);
      const size_t idx = (size_t)(b0 + lb) * HH + j0 + jj;
      stcg_f16(&g_hf[wb][idx], __float2half(hn));
      if (t == TT - 1) { out[128 + idx] = hn; out[128 + 65536 + idx] = cst; }
    }

    // inter-CTA barrier per batch group (32 CTAs each)
    if (t < TT - 1) {
      __syncthreads();
      if (tid == 0) {
        asm volatile("red.add.release.gpu.global.u32 [%0], %1;"
                     :: "l"(&g_bar[bg]), "r"(1u) : "memory");
        const unsigned tgt = (unsigned)(t + 1) * (unsigned)NJG;
        unsigned v;
        do {
          asm volatile("ld.acquire.gpu.global.u32 %0, [%1];"
                       : "=r"(v) : "l"(&g_bar[bg]) : "memory");
        } while (v < tgt);
      }
      __syncthreads();
    }
  }
}

// ---------------------------------------------------------------------------
__global__ void y_kernel(const float* __restrict__ fc_w,
                         const float* __restrict__ fc_b, float* __restrict__ out) {
  const int b = blockIdx.x;
  const int tid = threadIdx.x;
  const float* hr = out + 128 + (size_t)b * HH;
  float s = 0.f;
  for (int k = tid; k < HH; k += 128) s += hr[k] * fc_w[k];
#pragma unroll
  for (int o = 16; o; o >>= 1) s += __shfl_down_sync(0xffffffffu, s, o);
  __shared__ float red[4];
  if ((tid & 31) == 0) red[tid >> 5] = s;
  __syncthreads();
  if (tid == 0) out[b] = red[0] + red[1] + red[2] + red[3] + fc_b[0];
}

// ---------------------------------------------------------------------------
extern "C" void kernel_launch(void* const* d_in, const int* in_sizes, int n_in,
                              void* d_out, int out_size) {
  const int*   x    = (const int*)d_in[0];
  const float* h0   = (const float*)d_in[1];
  const float* c0   = (const float*)d_in[2];
  const float* emb  = (const float*)d_in[3];
  const float* W_ih = (const float*)d_in[4];
  const float* W_hh = (const float*)d_in[5];
  const float* b_ih = (const float*)d_in[6];
  const float* b_hh = (const float*)d_in[7];
  const float* fc_w = (const float*)d_in[8];
  const float* fc_b = (const float*)d_in[9];
  float* out = (float*)d_out;

  cudaFuncSetAttribute(lstm_mma_kernel, cudaFuncAttributeMaxDynamicSharedMemorySize,
                       SMEM_BYTES);
  cudaFuncSetAttribute(table_mma_kernel, cudaFuncAttributeMaxDynamicSharedMemorySize,
                       T_SMEM_BYTES);

  void* bar_p = nullptr;
  cudaGetSymbolAddress(&bar_p, g_bar);
  cudaMemsetAsync(bar_p, 0, sizeof(unsigned) * 8);                              // 0

  conv_f16_kernel<<<((VV + G4) * 76 + 255) / 256, 256>>>(emb, W_ih);            // 1
  table_mma_kernel<<<dim3(G4 / 64, (VV + 63) / 64), 256, T_SMEM_BYTES>>>(b_ih, b_hh); // 2
  split_h0_kernel<<<256, 256>>>(h0);                                            // 3
  lstm_mma_kernel<<<256, 256, SMEM_BYTES>>>(x, W_hh, c0, out);                  // 4
  y_kernel<<<BB, 128>>>(fc_w, fc_b, out);                                       // 5
}